// round 13
// baseline (speedup 1.0000x reference)
#include <cuda_runtime.h>
#include <cuda_bf16.h>

#define CH 256
#define CW 256
#define NS 64          // curve samples
#define NB 16          // batch
#define RPB 8          // rows per block (512 blocks -> single wave)
#define NPAIR (RPB/2)
#define NWARP 8
#define EPSF 1e-6f

struct P2 { float y, x; };

// ---- packed f32x2 helpers (Blackwell FFMA2 path, PTX-only) ----
__device__ __forceinline__ unsigned long long pk2(float a, float b) {
    unsigned long long r;
    asm("mov.b64 %0, {%1, %2};" : "=l"(r) : "f"(a), "f"(b));
    return r;
}
__device__ __forceinline__ void upk2(unsigned long long v, float& a, float& b) {
    asm("mov.b64 {%0, %1}, %2;" : "=f"(a), "=f"(b) : "l"(v));
}
__device__ __forceinline__ unsigned long long fma2(unsigned long long a,
                                                   unsigned long long b,
                                                   unsigned long long c) {
    unsigned long long r;
    asm("fma.rn.f32x2 %0, %1, %2, %3;" : "=l"(r) : "l"(a), "l"(b), "l"(c));
    return r;
}
__device__ __forceinline__ unsigned long long add2(unsigned long long a,
                                                   unsigned long long b) {
    unsigned long long r;
    asm("add.rn.f32x2 %0, %1, %2;" : "=l"(r) : "l"(a), "l"(b));
    return r;
}

__device__ __forceinline__ P2 bez4(P2 c0, P2 c1, P2 c2, P2 c3, float t) {
    float s = 1.0f - t;
    P2 a{ s*c0.y + t*c1.y, s*c0.x + t*c1.x };
    P2 b{ s*c1.y + t*c2.y, s*c1.x + t*c2.x };
    P2 c{ s*c2.y + t*c3.y, s*c2.x + t*c3.x };
    P2 d{ s*a.y  + t*b.y , s*a.x  + t*b.x  };
    P2 e{ s*b.y  + t*c.y , s*b.x  + t*c.x  };
    return P2{ s*d.y + t*e.y, s*d.x + t*e.x };
}

__global__ __launch_bounds__(256) void curve_kernel(
    const float* __restrict__ inputs,   // [16,4,2] (y,x) in [0,1]
    const float* __restrict__ widths,   // [16]
    const float* __restrict__ aas,      // [16]
    float* __restrict__ out)            // [16,256,256]
{
    __shared__ float  s_u[NWARP][NS];        // per-warp arclength scratch
    __shared__ float2 s_cand[NWARP][NS];     // per-warp candidate lists

    const int tid  = threadIdx.x;
    const int lane = tid & 31;
    const int wid  = tid >> 5;
    const int wc0  = wid << 5;               // warp's first column
    const int b    = blockIdx.y;
    const int r0   = blockIdx.x * RPB;
    const unsigned FULL = 0xffffffffu;

    P2 c0{ inputs[b*8+0]*256.0f, inputs[b*8+1]*256.0f };
    P2 c1{ inputs[b*8+2]*256.0f, inputs[b*8+3]*256.0f };
    P2 c2{ inputs[b*8+4]*256.0f, inputs[b*8+5]*256.0f };
    P2 c3{ inputs[b*8+6]*256.0f, inputs[b*8+7]*256.0f };

    const float w  = widths[b];
    const float w2 = w * w;
    const float fr0 = (float)r0;

    // ---- bbox cull: curve lies in control-point hull ⊂ bbox (+0.01 px margin) ----
    {
        float bxmin = fminf(fminf(c0.x, c1.x), fminf(c2.x, c3.x)) - 0.01f;
        float bxmax = fmaxf(fmaxf(c0.x, c1.x), fmaxf(c2.x, c3.x)) + 0.01f;
        float bymin = fminf(fminf(c0.y, c1.y), fminf(c2.y, c3.y)) - 0.01f;
        float bymax = fmaxf(fmaxf(c0.y, c1.y), fmaxf(c2.y, c3.y)) + 0.01f;
        float rx0 = (float)wc0;
        float gapx = fmaxf(0.0f, fmaxf(bxmin - (rx0 + 31.0f), rx0 - bxmax));
        float gapy = fmaxf(0.0f, fmaxf(bymin - (fr0 + 7.0f),  fr0 - bymax));
        if (fmaf(gapx, gapx, gapy * gapy) >= w2) {
            float4* zbase = (float4*)(out + ((size_t)b * CH + r0) * CW + wc0);
            int zf4 = lane & 7, zrr = lane >> 3;
            zbase[(size_t)zrr     * (CW/4) + zf4] = make_float4(0.f,0.f,0.f,0.f);
            zbase[(size_t)(zrr+4) * (CW/4) + zf4] = make_float4(0.f,0.f,0.f,0.f);
            return;
        }
    }

    // ---- warp-local prologue (only surviving warps; no block barrier anywhere) ----
    const float inv63 = 1.0f / 63.0f;
    P2 p0 = bez4(c0, c1, c2, c3, (float)lane * inv63);
    P2 p1 = bez4(c0, c1, c2, c3, (float)(lane + 32) * inv63);

    float pm0x = __shfl_up_sync(FULL, p0.x, 1);
    float pm0y = __shfl_up_sync(FULL, p0.y, 1);
    float pm1x = __shfl_up_sync(FULL, p1.x, 1);
    float pm1y = __shfl_up_sync(FULL, p1.y, 1);
    float b31x = __shfl_sync(FULL, p0.x, 31);
    float b31y = __shfl_sync(FULL, p0.y, 31);
    if (lane == 0) { pm1x = b31x; pm1y = b31y; }
    float seg0 = 0.0f;
    if (lane > 0) {
        float dy = p0.y - pm0y, dx = p0.x - pm0x;
        seg0 = sqrtf(dy*dy + dx*dx);
    }
    float dy1 = p1.y - pm1y, dx1 = p1.x - pm1x;
    float seg1 = sqrtf(dy1*dy1 + dx1*dx1);

    #pragma unroll
    for (int off = 1; off < 32; off <<= 1) {
        float v = __shfl_up_sync(FULL, seg0, off);
        if (lane >= off) seg0 += v;
    }
    #pragma unroll
    for (int off = 1; off < 32; off <<= 1) {
        float v = __shfl_up_sync(FULL, seg1, off);
        if (lane >= off) seg1 += v;
    }
    seg1 += __shfl_sync(FULL, seg0, 31);

    float total = __shfl_sync(FULL, seg1, 31);
    float rnorm = 1.0f / (total + EPSF);
    float u_lo = seg0 * rnorm;
    float u_hi = seg1 * rnorm;
    s_u[wid][lane]      = u_lo;
    s_u[wid][lane + 32] = u_hi;
    __syncwarp();
    const float u_last = __shfl_sync(FULL, u_hi, 31);

    float2 sv[2];
    #pragma unroll
    for (int k = 0; k < 2; k++) {
        float xq = (float)(lane + 32*k) * inv63;
        int pos = 0;
        #pragma unroll
        for (int st = 32; st > 0; st >>= 1) {
            int tt = pos + st;
            if (s_u[wid][tt - 1] <= xq) pos = tt;   // == linear count (u sorted)
        }
        int iss = pos; if (iss < 1) iss = 1; if (iss > NS-1) iss = NS-1;
        int j = iss - 1;
        float uj  = s_u[wid][j];
        float uj1 = s_u[wid][j+1];
        float tj  = (float)j * inv63;
        float tnew = tj + (xq - uj) * (inv63 / (uj1 - uj));
        if (xq > u_last) tnew = 1.0f;
        P2 p = bez4(c0, c1, c2, c3, tnew);
        sv[k] = make_float2(p.x, p.y);              // (x, y)
    }

    // ---- per-warp candidate build (from registers) ----
    int ccount = 0;
    {
        const float ccx = (float)wc0 + 15.5f;
        const float ccy = fr0 + 3.5f;
        #pragma unroll
        for (int k = 0; k < 2; k++) {
            float ax = fmaxf(fabsf(sv[k].x - ccx) - 15.5f, 0.0f);
            float ay = fmaxf(fabsf(sv[k].y - ccy) - 3.5f,  0.0f);
            float lb2 = fmaf(ax, ax, ay*ay);
            bool pred = lb2 < w2;
            unsigned mask = __ballot_sync(FULL, pred);
            int pos = __popc(mask & ((1u << lane) - 1u));
            if (pred) s_cand[wid][ccount + pos] = sv[k];
            ccount += __popc(mask);
        }
        __syncwarp();
    }

    float4* zbase = (float4*)(out + ((size_t)b * CH + r0) * CW + wc0);
    if (ccount == 0) {
        int zf4 = lane & 7, zrr = lane >> 3;
        zbase[(size_t)zrr     * (CW/4) + zf4] = make_float4(0.f,0.f,0.f,0.f);
        zbase[(size_t)(zrr+4) * (CW/4) + zf4] = make_float4(0.f,0.f,0.f,0.f);
        return;
    }

    // ---- min squared distance over candidates; clamp at w^2 (exact: any sample
    //      with true dist < w to a pixel in this region has lb < w -> candidate) ----
    float minv[RPB];
    #pragma unroll
    for (int i = 0; i < RPB; i++) minv[i] = w2;

    const float px = (float)(wc0 + lane);

    unsigned long long cpair[NPAIR];
    #pragma unroll
    for (int j = 0; j < NPAIR; j++)
        cpair[j] = pk2(-fr0 - (float)(2*j), -fr0 - (float)(2*j + 1));

    #pragma unroll 4
    for (int s = 0; s < ccount; s++) {
        float2 svv = s_cand[wid][s];
        float dx  = svv.x - px;
        float dx2 = dx * dx;
        unsigned long long dx2p = pk2(dx2, dx2);
        unsigned long long syp  = pk2(svv.y, svv.y);
        #pragma unroll
        for (int j = 0; j < NPAIR; j++) {
            unsigned long long dyp = add2(syp, cpair[j]);
            unsigned long long d2p = fma2(dyp, dyp, dx2p);
            float lo, hi;
            upk2(d2p, lo, hi);
            minv[2*j]     = fminf(minv[2*j],     lo);
            minv[2*j + 1] = fminf(minv[2*j + 1], hi);
        }
    }

    // ---- epilogue ----
    const float aa   = aas[b];
    const float invw = 1.0f / w;
    float* orow = out + ((size_t)b * CH + r0) * CW + wc0 + lane;
    #pragma unroll
    for (int i = 0; i < RPB; i++) {
        float md  = sqrtf(minv[i]);
        float v   = __powf(md * invw + EPSF, aa);
        float res = 1.0f - v;
        res = fminf(fmaxf(res, 0.0f), 1.0f);
        orow[(size_t)i * CW] = res;
    }
}

extern "C" void kernel_launch(void* const* d_in, const int* in_sizes, int n_in,
                              void* d_out, int out_size) {
    const float* inputs = (const float*)d_in[0];
    const float* widths = (const float*)d_in[1];
    const float* aas    = (const float*)d_in[2];
    float* out = (float*)d_out;
    dim3 grid(CH / RPB, NB);
    curve_kernel<<<grid, 256>>>(inputs, widths, aas, out);
}

// round 15
// speedup vs baseline: 1.5708x; 1.5708x over previous
#include <cuda_runtime.h>
#include <cuda_bf16.h>

#define CH 256
#define CW 256
#define NS 64          // curve samples
#define NB 16          // batch
#define RPB 8          // rows per block (512 blocks -> single wave)
#define NPAIR (RPB/2)
#define NWARP 8
#define EPSF 1e-6f

struct P2 { float y, x; };

// ---- packed f32x2 helpers (Blackwell FFMA2 path, PTX-only) ----
__device__ __forceinline__ unsigned long long pk2(float a, float b) {
    unsigned long long r;
    asm("mov.b64 %0, {%1, %2};" : "=l"(r) : "f"(a), "f"(b));
    return r;
}
__device__ __forceinline__ void upk2(unsigned long long v, float& a, float& b) {
    asm("mov.b64 {%0, %1}, %2;" : "=f"(a), "=f"(b) : "l"(v));
}
__device__ __forceinline__ unsigned long long fma2(unsigned long long a,
                                                   unsigned long long b,
                                                   unsigned long long c) {
    unsigned long long r;
    asm("fma.rn.f32x2 %0, %1, %2, %3;" : "=l"(r) : "l"(a), "l"(b), "l"(c));
    return r;
}
__device__ __forceinline__ unsigned long long add2(unsigned long long a,
                                                   unsigned long long b) {
    unsigned long long r;
    asm("add.rn.f32x2 %0, %1, %2;" : "=l"(r) : "l"(a), "l"(b));
    return r;
}

// ---- MUFU lg2/ex2 (fast-math pow pieces) ----
__device__ __forceinline__ float flg2(float x) {
    float r;
    asm("lg2.approx.f32 %0, %1;" : "=f"(r) : "f"(x));
    return r;
}
__device__ __forceinline__ float fex2(float x) {
    float r;
    asm("ex2.approx.f32 %0, %1;" : "=f"(r) : "f"(x));
    return r;
}

__device__ __forceinline__ P2 bez4(P2 c0, P2 c1, P2 c2, P2 c3, float t) {
    float s = 1.0f - t;
    P2 a{ s*c0.y + t*c1.y, s*c0.x + t*c1.x };
    P2 b{ s*c1.y + t*c2.y, s*c1.x + t*c2.x };
    P2 c{ s*c2.y + t*c3.y, s*c2.x + t*c3.x };
    P2 d{ s*a.y  + t*b.y , s*a.x  + t*b.x  };
    P2 e{ s*b.y  + t*c.y , s*b.x  + t*c.x  };
    return P2{ s*d.y + t*e.y, s*d.x + t*e.x };
}

// Rect(region 32x8)-to-rect(bbox) distance cull; identical formula everywhere
// so the prologue warp's band evaluation is bitwise identical to each warp's own.
__device__ __forceinline__ bool region_cull(float rx0, float ry0,
                                            float bxmin, float bxmax,
                                            float bymin, float bymax,
                                            float w2) {
    float gapx = fmaxf(0.0f, fmaxf(bxmin - (rx0 + 31.0f), rx0 - bxmax));
    float gapy = fmaxf(0.0f, fmaxf(bymin - (ry0 + 7.0f),  ry0 - bymax));
    return fmaf(gapx, gapx, gapy * gapy) >= w2;
}

__global__ __launch_bounds__(256) void curve_kernel(
    const float* __restrict__ inputs,   // [16,4,2] (y,x) in [0,1]
    const float* __restrict__ widths,   // [16]
    const float* __restrict__ aas,      // [16]
    float* __restrict__ out)            // [16,256,256]
{
    __shared__ float  s_u[NS];               // prologue scratch: normalized arclength
    __shared__ float2 s_s[NS];               // published samples: .x = x, .y = y
    __shared__ float2 s_cand[NWARP][NS];     // per-warp candidate lists

    const int tid  = threadIdx.x;
    const int lane = tid & 31;
    const int wid  = tid >> 5;
    const int wc0  = wid << 5;               // warp's first column
    const int b    = blockIdx.y;
    const int r0   = blockIdx.x * RPB;
    const unsigned FULL = 0xffffffffu;

    // Rotate prologue warp across blocks -> spreads serial chains over SMSPs.
    const int pwid = (blockIdx.x + blockIdx.y) & 7;

    P2 c0{ inputs[b*8+0]*256.0f, inputs[b*8+1]*256.0f };
    P2 c1{ inputs[b*8+2]*256.0f, inputs[b*8+3]*256.0f };
    P2 c2{ inputs[b*8+4]*256.0f, inputs[b*8+5]*256.0f };
    P2 c3{ inputs[b*8+6]*256.0f, inputs[b*8+7]*256.0f };

    const float w  = widths[b];
    const float w2 = w * w;

    // Control-point bbox (+0.01 px margin for fp32 curve-eval rounding).
    const float bxmin = fminf(fminf(c0.x, c1.x), fminf(c2.x, c3.x)) - 0.01f;
    const float bxmax = fmaxf(fmaxf(c0.x, c1.x), fmaxf(c2.x, c3.x)) + 0.01f;
    const float bymin = fminf(fminf(c0.y, c1.y), fminf(c2.y, c3.y)) - 0.01f;
    const float bymax = fmaxf(fmaxf(c0.y, c1.y), fmaxf(c2.y, c3.y)) + 0.01f;

    const float fr0 = (float)r0;
    const bool cullW = region_cull((float)wc0, fr0, bxmin, bxmax, bymin, bymax, w2);

    // Warp zero-fill: 32 cols x 8 rows = 2 STG.128 per lane.
    float4* zbase = (float4*)(out + ((size_t)b * CH + r0) * CW + wc0);
    const int zf4 = lane & 7;
    const int zrr = lane >> 3;               // 0..3

    if (wid == pwid) {
        // Band test: all 8 warp-regions culled? lanes 0..7 use the exact
        // per-region formula (bitwise identical to each warp's cullW).
        bool cj = (lane < NWARP)
            ? region_cull((float)(lane << 5), fr0, bxmin, bxmax, bymin, bymax, w2)
            : true;
        unsigned bbm = __ballot_sync(FULL, cj);
        if ((bbm & 0xffu) == 0xffu) {
            zbase[(size_t)zrr     * (CW/4) + zf4] = make_float4(0.f,0.f,0.f,0.f);
            zbase[(size_t)(zrr+4) * (CW/4) + zf4] = make_float4(0.f,0.f,0.f,0.f);
            return;                          // whole band zero; others exit on cullW
        }

        // ---- warp-local prologue (prologue warp only) ----
        const float inv63 = 1.0f / 63.0f;
        P2 p0 = bez4(c0, c1, c2, c3, (float)lane * inv63);
        P2 p1 = bez4(c0, c1, c2, c3, (float)(lane + 32) * inv63);

        float pm0x = __shfl_up_sync(FULL, p0.x, 1);
        float pm0y = __shfl_up_sync(FULL, p0.y, 1);
        float pm1x = __shfl_up_sync(FULL, p1.x, 1);
        float pm1y = __shfl_up_sync(FULL, p1.y, 1);
        float b31x = __shfl_sync(FULL, p0.x, 31);
        float b31y = __shfl_sync(FULL, p0.y, 31);
        if (lane == 0) { pm1x = b31x; pm1y = b31y; }
        float seg0 = 0.0f;
        if (lane > 0) {
            float dy = p0.y - pm0y, dx = p0.x - pm0x;
            seg0 = sqrtf(dy*dy + dx*dx);
        }
        float dy1 = p1.y - pm1y, dx1 = p1.x - pm1x;
        float seg1 = sqrtf(dy1*dy1 + dx1*dx1);

        #pragma unroll
        for (int off = 1; off < 32; off <<= 1) {
            float v = __shfl_up_sync(FULL, seg0, off);
            if (lane >= off) seg0 += v;
        }
        #pragma unroll
        for (int off = 1; off < 32; off <<= 1) {
            float v = __shfl_up_sync(FULL, seg1, off);
            if (lane >= off) seg1 += v;
        }
        seg1 += __shfl_sync(FULL, seg0, 31);

        float total = __shfl_sync(FULL, seg1, 31);
        float rnorm = 1.0f / (total + EPSF);
        float u_lo = seg0 * rnorm;
        float u_hi = seg1 * rnorm;
        s_u[lane]      = u_lo;
        s_u[lane + 32] = u_hi;
        __syncwarp();
        const float u_last = __shfl_sync(FULL, u_hi, 31);

        #pragma unroll
        for (int k = 0; k < 2; k++) {
            float xq = (float)(lane + 32*k) * inv63;
            int pos = 0;
            #pragma unroll
            for (int st = 32; st > 0; st >>= 1) {
                int tt = pos + st;
                if (s_u[tt - 1] <= xq) pos = tt;     // == linear count (u sorted)
            }
            int iss = pos; if (iss < 1) iss = 1; if (iss > NS-1) iss = NS-1;
            int j = iss - 1;
            float uj  = s_u[j];
            float uj1 = s_u[j+1];
            float tj  = (float)j * inv63;
            float tnew = tj + (xq - uj) * (inv63 / (uj1 - uj));
            if (xq > u_last) tnew = 1.0f;
            P2 p = bez4(c0, c1, c2, c3, tnew);
            s_s[lane + 32*k] = make_float2(p.x, p.y);   // (x, y)
        }

        if (cullW) {    // own region zero; samples published, still hit barrier
            zbase[(size_t)zrr     * (CW/4) + zf4] = make_float4(0.f,0.f,0.f,0.f);
            zbase[(size_t)(zrr+4) * (CW/4) + zf4] = make_float4(0.f,0.f,0.f,0.f);
        }
    } else {
        if (cullW) {    // exit before barrier: exited threads are released
            zbase[(size_t)zrr     * (CW/4) + zf4] = make_float4(0.f,0.f,0.f,0.f);
            zbase[(size_t)(zrr+4) * (CW/4) + zf4] = make_float4(0.f,0.f,0.f,0.f);
            return;
        }
    }

    __syncthreads();       // only non-exited threads arrive
    if (cullW) return;     // (only the prologue warp can reach here culled)

    // ================= per-warp candidate build (sample-exact lb) =================
    int ccount = 0;
    {
        const float ccx = (float)wc0 + 15.5f;
        const float ccy = fr0 + 3.5f;
        #pragma unroll
        for (int k = 0; k < 2; k++) {
            float2 svv = s_s[lane + 32*k];
            float ax = fmaxf(fabsf(svv.x - ccx) - 15.5f, 0.0f);
            float ay = fmaxf(fabsf(svv.y - ccy) - 3.5f,  0.0f);
            float lb2 = fmaf(ax, ax, ay*ay);
            bool pred = lb2 < w2;
            unsigned mask = __ballot_sync(FULL, pred);
            int pos = __popc(mask & ((1u << lane) - 1u));
            if (pred) s_cand[wid][ccount + pos] = svv;
            ccount += __popc(mask);
        }
        __syncwarp();
    }

    if (ccount == 0) {
        zbase[(size_t)zrr     * (CW/4) + zf4] = make_float4(0.f,0.f,0.f,0.f);
        zbase[(size_t)(zrr+4) * (CW/4) + zf4] = make_float4(0.f,0.f,0.f,0.f);
        return;
    }

    // ---- min squared distance over candidates; clamp at w^2 (exact: any sample
    //      with true dist < w to a pixel in this region has lb < w -> candidate) ----
    float minv[RPB];
    #pragma unroll
    for (int i = 0; i < RPB; i++) minv[i] = w2;

    const float px = (float)(wc0 + lane);

    unsigned long long cpair[NPAIR];
    #pragma unroll
    for (int j = 0; j < NPAIR; j++)
        cpair[j] = pk2(-fr0 - (float)(2*j), -fr0 - (float)(2*j + 1));

    #pragma unroll 4
    for (int s = 0; s < ccount; s++) {
        float2 svv = s_cand[wid][s];
        float dx  = svv.x - px;
        float dx2 = dx * dx;
        unsigned long long dx2p = pk2(dx2, dx2);
        unsigned long long syp  = pk2(svv.y, svv.y);
        #pragma unroll
        for (int j = 0; j < NPAIR; j++) {
            unsigned long long dyp = add2(syp, cpair[j]);
            unsigned long long d2p = fma2(dyp, dyp, dx2p);
            float lo, hi;
            upk2(d2p, lo, hi);
            minv[2*j]     = fminf(minv[2*j],     lo);
            minv[2*j + 1] = fminf(minv[2*j + 1], hi);
        }
    }

    // ---- epilogue: 1 - ((md/w)+eps)^aa  ≈  1 - exp2(0.5*aa*log2(d2/w2))
    //      (drops eps inside pow: |delta| <= aa*eps ~ 4e-6 absolute, clip-safe;
    //       d2=0 -> lg2=-inf -> ex2=0 -> res=1, matching ref ~1-eps^aa)
    const float aa    = aas[b];
    const float invw2 = 1.0f / w2;
    const float haa   = 0.5f * aa;
    float* orow = out + ((size_t)b * CH + r0) * CW + wc0 + lane;
    #pragma unroll
    for (int i = 0; i < RPB; i++) {
        float q   = minv[i] * invw2;            // (md/w)^2 in [0,1]
        float res = 1.0f - fex2(haa * flg2(q));
        res = fminf(fmaxf(res, 0.0f), 1.0f);
        orow[(size_t)i * CW] = res;
    }
}

extern "C" void kernel_launch(void* const* d_in, const int* in_sizes, int n_in,
                              void* d_out, int out_size) {
    const float* inputs = (const float*)d_in[0];
    const float* widths = (const float*)d_in[1];
    const float* aas    = (const float*)d_in[2];
    float* out = (float*)d_out;
    dim3 grid(CH / RPB, NB);
    curve_kernel<<<grid, 256>>>(inputs, widths, aas, out);
}